// round 2
// baseline (speedup 1.0000x reference)
#include <cuda_runtime.h>

#define TOK 4096          // S*B
#define QKV_ELEMS ((size_t)TOK * 6144)   // [t][n][e] e = h*64+j

// ---- scratch (static device globals; no runtime allocation) ----
__device__ float g_comp[TOK * 8];
__device__ float g_q[QKV_ELEMS];
__device__ float g_k[QKV_ELEMS];
__device__ float g_v[QKV_ELEMS];
__device__ float g_o[QKV_ELEMS];

// ============================================================
// Kernel A: competition gating. One warp per token.
// comp[t][n] = softmax_n( dot(x[t, n*128 : n*128+128], w_comp[n]) )
// ============================================================
__global__ void comp_kernel(const float* __restrict__ x,
                            const float* __restrict__ wc) {
    int gtid = blockIdx.x * blockDim.x + threadIdx.x;
    int t    = gtid >> 5;
    int lane = gtid & 31;
    if (t >= TOK) return;
    const float* xr = x + (size_t)t * 1024;

    float logit[8];
#pragma unroll
    for (int n = 0; n < 8; n++) {
        const float* xb = xr + n * 128;
        const float* wb = wc + n * 128;
        float p = xb[lane]      * wb[lane]
                + xb[lane + 32] * wb[lane + 32]
                + xb[lane + 64] * wb[lane + 64]
                + xb[lane + 96] * wb[lane + 96];
#pragma unroll
        for (int o = 16; o > 0; o >>= 1) p += __shfl_xor_sync(0xffffffffu, p, o);
        logit[n] = p;   // all lanes hold the full sum
    }
    float mx = logit[0];
#pragma unroll
    for (int n = 1; n < 8; n++) mx = fmaxf(mx, logit[n]);
    float s = 0.f, ev = 0.f;
#pragma unroll
    for (int n = 0; n < 8; n++) {
        float e = __expf(logit[n] - mx);
        s += e;
        if (lane == n) ev = e;
    }
    if (lane < 8) g_comp[t * 8 + lane] = ev / s;
}

// ============================================================
// Shared SGEMM: per z-block n,  C = A_n @ W_n  (optional comp row-scale)
//   A_n = Aall + n*a_blk, row stride lda       [M=4096, K]
//   W_n = Wall + n*K*ldb + blockIdx.y*128      [K, 128-col tile], row stride ldb
//   C_n = Call + n*c_blk, row stride ldc
// Tile 128x128, BK=32, 256 threads, 8x8 microtile.
// ============================================================
__global__ __launch_bounds__(256, 2)
void gemm_kernel(const float* __restrict__ Aall, int lda, int a_blk,
                 const float* __restrict__ Wall, int ldb, int K,
                 float* __restrict__ Call, int ldc, int c_blk,
                 const float* __restrict__ comp) {
    __shared__ __align__(16) float As[32 * 132];  // [k][m], padded
    __shared__ __align__(16) float Bs[32 * 128];  // [k][e]

    const int n   = blockIdx.z;
    const float* A = Aall + (size_t)blockIdx.x * 128 * lda + n * a_blk;
    const float* W = Wall + (size_t)n * K * ldb + blockIdx.y * 128;

    const int tid = threadIdx.x;
    const int tx  = tid & 15;    // col dir
    const int ty  = tid >> 4;    // row dir

    float acc[8][8];
#pragma unroll
    for (int i = 0; i < 8; i++)
#pragma unroll
        for (int j = 0; j < 8; j++) acc[i][j] = 0.f;

    const int ak4 = tid & 7;     // float4 index along k
    const int am  = tid >> 3;    // 0..31
    const int be4 = tid & 31;
    const int bk  = tid >> 5;    // 0..7

    const int nchunks = K >> 5;
    for (int kc = 0; kc < nchunks; kc++) {
        const int k0 = kc << 5;
        // A tile: 128m x 32k, stored transposed [k][m]
#pragma unroll
        for (int p = 0; p < 4; p++) {
            int m = am + p * 32;
            float4 av = *(const float4*)(A + (size_t)m * lda + k0 + ak4 * 4);
            As[(ak4 * 4 + 0) * 132 + m] = av.x;
            As[(ak4 * 4 + 1) * 132 + m] = av.y;
            As[(ak4 * 4 + 2) * 132 + m] = av.z;
            As[(ak4 * 4 + 3) * 132 + m] = av.w;
        }
        // B tile: 32k x 128e
#pragma unroll
        for (int p = 0; p < 4; p++) {
            int k = bk + p * 8;
            *(float4*)(Bs + k * 128 + be4 * 4) =
                *(const float4*)(W + (size_t)(k0 + k) * ldb + be4 * 4);
        }
        __syncthreads();
#pragma unroll
        for (int k = 0; k < 32; k++) {
            float4 a0 = *(const float4*)(As + k * 132 + ty * 8);
            float4 a1 = *(const float4*)(As + k * 132 + ty * 8 + 4);
            float4 b0 = *(const float4*)(Bs + k * 128 + tx * 8);
            float4 b1 = *(const float4*)(Bs + k * 128 + tx * 8 + 4);
            float ar[8] = {a0.x, a0.y, a0.z, a0.w, a1.x, a1.y, a1.z, a1.w};
            float br[8] = {b0.x, b0.y, b0.z, b0.w, b1.x, b1.y, b1.z, b1.w};
#pragma unroll
            for (int i = 0; i < 8; i++)
#pragma unroll
                for (int j = 0; j < 8; j++)
                    acc[i][j] = fmaf(ar[i], br[j], acc[i][j]);
        }
        __syncthreads();
    }

    const int row0 = blockIdx.x * 128 + ty * 8;
    const int col  = blockIdx.y * 128 + tx * 8;
#pragma unroll
    for (int i = 0; i < 8; i++) {
        int row  = row0 + i;
        float sc = comp ? comp[row * 8 + n] : 1.0f;
        float4 o0 = make_float4(acc[i][0] * sc, acc[i][1] * sc,
                                acc[i][2] * sc, acc[i][3] * sc);
        float4 o1 = make_float4(acc[i][4] * sc, acc[i][5] * sc,
                                acc[i][6] * sc, acc[i][7] * sc);
        float* Cp = Call + (size_t)n * c_blk + (size_t)row * ldc + col;
        *(float4*)Cp       = o0;
        *(float4*)(Cp + 4) = o1;
    }
}

// ============================================================
// Kernel C: block-attention per token. 1 CTA = 1 token, 12 warps = 12 heads.
// q,k,v in [t][n][h*64+j] scratch. Out to g_o[t][n][h*64+j],
// score_mean to d_out[4194304 + t*64 + n*8 + m].
// ============================================================
#define SMEM_ATTN ((12*8*65 + 12*8*65 + 12*8*64 + 12*64) * 4)

__global__ void attn_kernel(float* __restrict__ out) {
    extern __shared__ float sm[];
    float* sq = sm;                    // 12 * 8 * 65 = 6240
    float* sk = sq + 6240;             // 6240
    float* sv = sk + 6240;             // 12 * 8 * 64 = 6144
    float* ss = sv + 6144;             // 12 * 64 = 768

    const int t   = blockIdx.x;
    const int tid = threadIdx.x;       // 384
    const size_t base = (size_t)t * 6144;

#pragma unroll
    for (int it = 0; it < 16; it++) {
        int idx = it * 384 + tid;
        int nn  = idx / 768;
        int r   = idx - nn * 768;
        int h   = r >> 6;
        int j   = r & 63;
        sq[h * 520 + nn * 65 + j] = g_q[base + idx] * 0.125f;  // hd^-0.5
        sk[h * 520 + nn * 65 + j] = g_k[base + idx];
        sv[h * 512 + nn * 64 + j] = g_v[base + idx];
    }
    __syncthreads();

    const int w    = tid >> 5;   // head
    const int lane = tid & 31;
    float* q = sq + w * 520;
    float* k = sk + w * 520;
    float* v = sv + w * 512;
    float* s = ss + w * 64;

    const int nr = lane >> 3;    // 0..3 (s0), nr+4 (s1)
    const int mc = lane & 7;

    float s0 = 0.f, s1 = 0.f;
#pragma unroll
    for (int j = 0; j < 64; j++) {
        float kv = k[mc * 65 + j];
        s0 = fmaf(q[nr * 65 + j], kv, s0);
        s1 = fmaf(q[(nr + 4) * 65 + j], kv, s1);
    }
    // softmax over m within groups of 8 lanes (same row n)
    float m0 = s0, m1 = s1;
#pragma unroll
    for (int o = 1; o < 8; o <<= 1) {
        m0 = fmaxf(m0, __shfl_xor_sync(0xffffffffu, m0, o));
        m1 = fmaxf(m1, __shfl_xor_sync(0xffffffffu, m1, o));
    }
    float e0 = __expf(s0 - m0), e1 = __expf(s1 - m1);
    float d0 = e0, d1 = e1;
#pragma unroll
    for (int o = 1; o < 8; o <<= 1) {
        d0 += __shfl_xor_sync(0xffffffffu, d0, o);
        d1 += __shfl_xor_sync(0xffffffffu, d1, o);
    }
    float a0 = e0 / d0, a1 = e1 / d1;
    s[nr * 8 + mc]       = a0;
    s[(nr + 4) * 8 + mc] = a1;
    __syncwarp();

    // out[n][j] = sum_m attn[n][m] * v[m][j]
#pragma unroll
    for (int nn = 0; nn < 8; nn++) {
        float acc0 = 0.f, acc1 = 0.f;
#pragma unroll
        for (int mm = 0; mm < 8; mm++) {
            float av = s[nn * 8 + mm];
            acc0 = fmaf(av, v[mm * 64 + lane], acc0);
            acc1 = fmaf(av, v[mm * 64 + 32 + lane], acc1);
        }
        g_o[base + nn * 768 + w * 64 + lane]      = acc0;
        g_o[base + nn * 768 + w * 64 + 32 + lane] = acc1;
    }
    __syncthreads();

    // score_mean = mean over heads
    if (tid < 64) {
        float sum = 0.f;
#pragma unroll
        for (int h = 0; h < 12; h++) sum += ss[h * 64 + tid];
        out[4194304 + (size_t)t * 64 + tid] = sum * (1.0f / 12.0f);
    }
}

// ============================================================
// launch
// ============================================================
extern "C" void kernel_launch(void* const* d_in, const int* in_sizes, int n_in,
                              void* d_out, int out_size) {
    const float* x  = (const float*)d_in[0];
    const float* wc = (const float*)d_in[1];
    const float* wq = (const float*)d_in[2];
    const float* wk = (const float*)d_in[3];
    const float* wv = (const float*)d_in[4];
    const float* wf = (const float*)d_in[5];
    float* out = (float*)d_out;

    float *gq, *gk, *gv, *go, *gc;
    cudaGetSymbolAddress((void**)&gq, g_q);
    cudaGetSymbolAddress((void**)&gk, g_k);
    cudaGetSymbolAddress((void**)&gv, g_v);
    cudaGetSymbolAddress((void**)&go, g_o);
    cudaGetSymbolAddress((void**)&gc, g_comp);

    cudaFuncSetAttribute(attn_kernel,
                         cudaFuncAttributeMaxDynamicSharedMemorySize, SMEM_ATTN);

    // A: gating
    comp_kernel<<<512, 256>>>(x, wc);

    // B: QKV block-GEMMs (epilogue scales rows by comp)
    dim3 gB(32, 6, 8);   // 4096/128 m-tiles, 768/128 e-tiles, 8 blocks
    gemm_kernel<<<gB, 256>>>(x, 1024, 128, wq, 768, 128, gq, 6144, 768, gc);
    gemm_kernel<<<gB, 256>>>(x, 1024, 128, wk, 768, 128, gk, 6144, 768, gc);
    gemm_kernel<<<gB, 256>>>(x, 1024, 128, wv, 768, 128, gv, 6144, 768, gc);

    // C: attention over the block axis + score_mean
    attn_kernel<<<TOK, 384, SMEM_ATTN>>>(out);

    // D: final block-GEMMs -> d_out[t*1024 + n*128 + d]
    dim3 gD(32, 1, 8);
    gemm_kernel<<<gD, 256>>>(go, 6144, 768, wf, 128, 768, out, 1024, 128, nullptr);
}

// round 4
// speedup vs baseline: 2.0570x; 2.0570x over previous
#include <cuda_runtime.h>
#include <cstdint>

#define TOK 4096
#define QKV_ELEMS ((size_t)TOK * 6144)

// ---- scratch ----
__device__ float g_comp[TOK * 8];
__device__ float g_q[QKV_ELEMS];
__device__ float g_k[QKV_ELEMS];
__device__ float g_v[QKV_ELEMS];
__device__ float g_o[QKV_ELEMS];

// ============================================================
// helpers
// ============================================================
__device__ __forceinline__ uint32_t smem_u32(const void* p) {
    uint32_t a;
    asm("{ .reg .u64 t; cvta.to.shared.u64 t, %1; cvt.u32.u64 %0, t; }"
        : "=r"(a) : "l"(p));
    return a;
}
__device__ __forceinline__ uint32_t tf32r(float x) {
    uint32_t u;
    asm("cvt.rna.tf32.f32 %0, %1;" : "=r"(u) : "f"(x));
    return u;
}
__device__ __forceinline__ void cp16(uint32_t dst, const void* src) {
    asm volatile("cp.async.ca.shared.global [%0], [%1], 16;"
                 :: "r"(dst), "l"(src));
}
#define CP_COMMIT() asm volatile("cp.async.commit_group;" ::: "memory")
#define CP_WAIT(n)  asm volatile("cp.async.wait_group %0;" :: "n"(n) : "memory")

__device__ __forceinline__ void mma_tf32(float* c, const uint32_t* a,
                                         const uint32_t* b) {
    asm volatile(
        "mma.sync.aligned.m16n8k8.row.col.f32.tf32.tf32.f32 "
        "{%0,%1,%2,%3}, {%4,%5,%6,%7}, {%8,%9}, {%0,%1,%2,%3};"
        : "+f"(c[0]), "+f"(c[1]), "+f"(c[2]), "+f"(c[3])
        : "r"(a[0]), "r"(a[1]), "r"(a[2]), "r"(a[3]), "r"(b[0]), "r"(b[1]));
}

// ============================================================
// Kernel A: competition gating
// ============================================================
__global__ void comp_kernel(const float* __restrict__ x,
                            const float* __restrict__ wc) {
    int gtid = blockIdx.x * blockDim.x + threadIdx.x;
    int t    = gtid >> 5;
    int lane = gtid & 31;
    if (t >= TOK) return;
    const float* xr = x + (size_t)t * 1024;

    float logit[8];
#pragma unroll
    for (int n = 0; n < 8; n++) {
        const float* xb = xr + n * 128;
        const float* wb = wc + n * 128;
        float p = xb[lane]      * wb[lane]
                + xb[lane + 32] * wb[lane + 32]
                + xb[lane + 64] * wb[lane + 64]
                + xb[lane + 96] * wb[lane + 96];
#pragma unroll
        for (int o = 16; o > 0; o >>= 1) p += __shfl_xor_sync(0xffffffffu, p, o);
        logit[n] = p;
    }
    float mx = logit[0];
#pragma unroll
    for (int n = 1; n < 8; n++) mx = fmaxf(mx, logit[n]);
    float s = 0.f, ev = 0.f;
#pragma unroll
    for (int n = 0; n < 8; n++) {
        float e = __expf(logit[n] - mx);
        s += e;
        if (lane == n) ev = e;
    }
    if (lane < 8) g_comp[t * 8 + lane] = ev / s;
}

// ============================================================
// tf32 mma.sync block-GEMM.
//   grid = (32 m-tiles, TPM*nmats, 8 blocks), 256 threads (8 warps, 4x2)
//   per CTA: C[128 x 128] = A_n[128 x K] @ W_n[K x 128]
//   A smem [m][k] stride 36; B smem [k][n] stride 136 (both conflict-free)
//   cp.async double-buffered k-chunks of 32.
// ============================================================
#define AS_STRIDE 36
#define BS_STRIDE 136
#define A_BUF_FLTS (128 * AS_STRIDE)            // 4608
#define B_BUF_FLTS (32 * BS_STRIDE)             // 4352
#define SMEM_GEMM ((2 * A_BUF_FLTS + 2 * B_BUF_FLTS) * 4)  // 71680 B

__global__ __launch_bounds__(256, 2)
void gemm_mma(const float* __restrict__ Abase, int lda, int a_blk,
              const float* __restrict__ W0, const float* __restrict__ W1,
              const float* __restrict__ W2, int ldb, int w_blk, int TPM,
              float* __restrict__ C0, float* __restrict__ C1,
              float* __restrict__ C2, int ldc, int c_blk,
              int KC, const float* __restrict__ comp) {
    extern __shared__ __align__(16) float sm[];
    float* As[2] = { sm, sm + A_BUF_FLTS };
    float* Bs[2] = { sm + 2 * A_BUF_FLTS, sm + 2 * A_BUF_FLTS + B_BUF_FLTS };
    const uint32_t sbase = smem_u32(sm);

    const int tid  = threadIdx.x;
    const int wid  = tid >> 5;
    const int lane = tid & 31;
    const int wm   = wid & 3;        // warp row  (4)
    const int wn   = wid >> 2;       // warp col  (2)
    const int g    = lane >> 2;      // 0..7
    const int t    = lane & 3;       // 0..3

    const int mt   = blockIdx.x;
    const int yy   = blockIdx.y;
    const int zb   = blockIdx.z;
    const int mat  = yy / TPM;
    const int col0 = (yy % TPM) * 128;

    const float* W = (mat == 0 ? W0 : (mat == 1 ? W1 : W2)) +
                     (size_t)zb * w_blk + col0;
    float* C = (mat == 0 ? C0 : (mat == 1 ? C1 : C2)) +
               (size_t)zb * c_blk + col0;
    const float* A = Abase + (size_t)mt * 128 * lda + (size_t)zb * a_blk;

    // cp.async index precompute
    const int a_m  = tid >> 3;          // with p*32 added: rows 0..127 over 4 iters
    const int a_k4 = tid & 7;
    const int b_k  = tid >> 5;          // + p*8
    const int b_e4 = tid & 31;

    float acc[2][8][4];
#pragma unroll
    for (int i = 0; i < 2; i++)
#pragma unroll
        for (int j = 0; j < 8; j++)
#pragma unroll
            for (int c = 0; c < 4; c++) acc[i][j][c] = 0.f;

    // ---- prefetch chunk 0 ----
    {
        uint32_t ad = sbase;  // As[0]
        uint32_t bd = sbase + (uint32_t)(2 * A_BUF_FLTS) * 4;
#pragma unroll
        for (int p = 0; p < 4; p++) {
            int m = a_m + p * 32;
            cp16(ad + (uint32_t)(m * AS_STRIDE + a_k4 * 4) * 4,
                 A + (size_t)m * lda + a_k4 * 4);
        }
#pragma unroll
        for (int p = 0; p < 4; p++) {
            int k = b_k + p * 8;
            cp16(bd + (uint32_t)(k * BS_STRIDE + b_e4 * 4) * 4,
                 W + (size_t)k * ldb + b_e4 * 4);
        }
        CP_COMMIT();
    }

    for (int kc = 0; kc < KC; kc++) {
        const int cur = kc & 1;
        if (kc + 1 < KC) {
            const int nxt = cur ^ 1;
            const int k0 = (kc + 1) * 32;
            uint32_t ad = sbase + (uint32_t)(nxt * A_BUF_FLTS) * 4;
            uint32_t bd = sbase + (uint32_t)(2 * A_BUF_FLTS + nxt * B_BUF_FLTS) * 4;
#pragma unroll
            for (int p = 0; p < 4; p++) {
                int m = a_m + p * 32;
                cp16(ad + (uint32_t)(m * AS_STRIDE + a_k4 * 4) * 4,
                     A + (size_t)m * lda + k0 + a_k4 * 4);
            }
#pragma unroll
            for (int p = 0; p < 4; p++) {
                int k = b_k + p * 8;
                cp16(bd + (uint32_t)(k * BS_STRIDE + b_e4 * 4) * 4,
                     W + (size_t)(k0 + k) * ldb + b_e4 * 4);
            }
            CP_COMMIT();
            CP_WAIT(1);
        } else {
            CP_WAIT(0);
        }
        __syncthreads();

        const float* as = As[cur];
        const float* bs = Bs[cur];
#pragma unroll
        for (int ks = 0; ks < 4; ks++) {
            const int kk = ks * 8;
            uint32_t af[2][4];
#pragma unroll
            for (int i = 0; i < 2; i++) {
                const int r0 = wm * 32 + i * 16;
                af[i][0] = tf32r(as[(r0 + g)     * AS_STRIDE + kk + t]);
                af[i][1] = tf32r(as[(r0 + g + 8) * AS_STRIDE + kk + t]);
                af[i][2] = tf32r(as[(r0 + g)     * AS_STRIDE + kk + t + 4]);
                af[i][3] = tf32r(as[(r0 + g + 8) * AS_STRIDE + kk + t + 4]);
            }
            uint32_t bf[8][2];
#pragma unroll
            for (int j = 0; j < 8; j++) {
                const int c = wn * 64 + j * 8 + g;
                bf[j][0] = tf32r(bs[(kk + t)     * BS_STRIDE + c]);
                bf[j][1] = tf32r(bs[(kk + t + 4) * BS_STRIDE + c]);
            }
#pragma unroll
            for (int i = 0; i < 2; i++)
#pragma unroll
                for (int j = 0; j < 8; j++)
                    mma_tf32(acc[i][j], af[i], bf[j]);
        }
        __syncthreads();
    }

    // ---- epilogue ----
#pragma unroll
    for (int i = 0; i < 2; i++) {
        const int r0 = mt * 128 + wm * 32 + i * 16 + g;
        const int r1 = r0 + 8;
        float sc0 = 1.f, sc1 = 1.f;
        if (comp) { sc0 = comp[r0 * 8 + zb]; sc1 = comp[r1 * 8 + zb]; }
        float* Cr0 = C + (size_t)r0 * ldc;
        float* Cr1 = C + (size_t)r1 * ldc;
#pragma unroll
        for (int j = 0; j < 8; j++) {
            const int c = wn * 64 + j * 8 + 2 * t;
            float2 v0 = make_float2(acc[i][j][0] * sc0, acc[i][j][1] * sc0);
            float2 v1 = make_float2(acc[i][j][2] * sc1, acc[i][j][3] * sc1);
            *(float2*)(Cr0 + c) = v0;
            *(float2*)(Cr1 + c) = v1;
        }
    }
}

// ============================================================
// Kernel C: block-attention per token (unchanged)
// ============================================================
#define SMEM_ATTN ((12*8*65 + 12*8*65 + 12*8*64 + 12*64) * 4)

__global__ void attn_kernel(float* __restrict__ out) {
    extern __shared__ float smf[];
    float* sq = smf;
    float* sk = sq + 6240;
    float* sv = sk + 6240;
    float* ss = sv + 6144;

    const int t   = blockIdx.x;
    const int tid = threadIdx.x;
    const size_t base = (size_t)t * 6144;

#pragma unroll
    for (int it = 0; it < 16; it++) {
        int idx = it * 384 + tid;
        int nn  = idx / 768;
        int r   = idx - nn * 768;
        int h   = r >> 6;
        int j   = r & 63;
        sq[h * 520 + nn * 65 + j] = g_q[base + idx] * 0.125f;
        sk[h * 520 + nn * 65 + j] = g_k[base + idx];
        sv[h * 512 + nn * 64 + j] = g_v[base + idx];
    }
    __syncthreads();

    const int w    = tid >> 5;
    const int lane = tid & 31;
    float* q = sq + w * 520;
    float* k = sk + w * 520;
    float* v = sv + w * 512;
    float* s = ss + w * 64;

    const int nr = lane >> 3;
    const int mc = lane & 7;

    float s0 = 0.f, s1 = 0.f;
#pragma unroll
    for (int j = 0; j < 64; j++) {
        float kv = k[mc * 65 + j];
        s0 = fmaf(q[nr * 65 + j], kv, s0);
        s1 = fmaf(q[(nr + 4) * 65 + j], kv, s1);
    }
    float m0 = s0, m1 = s1;
#pragma unroll
    for (int o = 1; o < 8; o <<= 1) {
        m0 = fmaxf(m0, __shfl_xor_sync(0xffffffffu, m0, o));
        m1 = fmaxf(m1, __shfl_xor_sync(0xffffffffu, m1, o));
    }
    float e0 = __expf(s0 - m0), e1 = __expf(s1 - m1);
    float d0 = e0, d1 = e1;
#pragma unroll
    for (int o = 1; o < 8; o <<= 1) {
        d0 += __shfl_xor_sync(0xffffffffu, d0, o);
        d1 += __shfl_xor_sync(0xffffffffu, d1, o);
    }
    float a0 = e0 / d0, a1 = e1 / d1;
    s[nr * 8 + mc]       = a0;
    s[(nr + 4) * 8 + mc] = a1;
    __syncwarp();

#pragma unroll
    for (int nn = 0; nn < 8; nn++) {
        float acc0 = 0.f, acc1 = 0.f;
#pragma unroll
        for (int mm = 0; mm < 8; mm++) {
            float av = s[nn * 8 + mm];
            acc0 = fmaf(av, v[mm * 64 + lane], acc0);
            acc1 = fmaf(av, v[mm * 64 + 32 + lane], acc1);
        }
        g_o[base + nn * 768 + w * 64 + lane]      = acc0;
        g_o[base + nn * 768 + w * 64 + 32 + lane] = acc1;
    }
    __syncthreads();

    if (tid < 64) {
        float sum = 0.f;
#pragma unroll
        for (int h = 0; h < 12; h++) sum += ss[h * 64 + tid];
        out[4194304 + (size_t)t * 64 + tid] = sum * (1.0f / 12.0f);
    }
}

// ============================================================
// launch
// ============================================================
extern "C" void kernel_launch(void* const* d_in, const int* in_sizes, int n_in,
                              void* d_out, int out_size) {
    const float* x  = (const float*)d_in[0];
    const float* wc = (const float*)d_in[1];
    const float* wq = (const float*)d_in[2];
    const float* wk = (const float*)d_in[3];
    const float* wv = (const float*)d_in[4];
    const float* wf = (const float*)d_in[5];
    float* out = (float*)d_out;

    float *gq, *gk, *gv, *go, *gc;
    cudaGetSymbolAddress((void**)&gq, g_q);
    cudaGetSymbolAddress((void**)&gk, g_k);
    cudaGetSymbolAddress((void**)&gv, g_v);
    cudaGetSymbolAddress((void**)&go, g_o);
    cudaGetSymbolAddress((void**)&gc, g_comp);

    cudaFuncSetAttribute(attn_kernel,
                         cudaFuncAttributeMaxDynamicSharedMemorySize, SMEM_ATTN);
    cudaFuncSetAttribute(gemm_mma,
                         cudaFuncAttributeMaxDynamicSharedMemorySize, SMEM_GEMM);

    // A: gating
    comp_kernel<<<512, 256>>>(x, wc);

    // B: fused QKV tf32 GEMMs. 18 = 3 matrices x 6 col-tiles. K=128 -> KC=4.
    dim3 gB(32, 18, 8);
    gemm_mma<<<gB, 256, SMEM_GEMM>>>(
        x, 1024, 128,
        wq, wk, wv, 768, 98304, 6,
        gq, gk, gv, 6144, 768,
        4, gc);

    // C: attention over the block axis + score_mean
    attn_kernel<<<TOK, 384, SMEM_ATTN>>>(out);

    // D: final tf32 GEMM. K=768 -> KC=24.
    dim3 gD(32, 1, 8);
    gemm_mma<<<gD, 256, SMEM_GEMM>>>(
        go, 6144, 768,
        wf, wf, wf, 128, 98304, 1,
        out, out, out, 1024, 128,
        24, nullptr);
}

// round 5
// speedup vs baseline: 2.1897x; 1.0645x over previous
#include <cuda_runtime.h>
#include <cstdint>

#define TOK 4096
#define QKV_ELEMS ((size_t)TOK * 6144)

// ---- scratch ----
__device__ float g_comp[TOK * 8];
__device__ float g_q[QKV_ELEMS];
__device__ float g_k[QKV_ELEMS];
__device__ float g_v[QKV_ELEMS];
__device__ float g_o[QKV_ELEMS];
// tf32-pre-rounded operands
__device__ float g_xr[4194304];
__device__ float g_wqr[786432];
__device__ float g_wkr[786432];
__device__ float g_wvr[786432];
__device__ float g_wfr[786432];

// ============================================================
// helpers
// ============================================================
__device__ __forceinline__ uint32_t smem_u32(const void* p) {
    uint32_t a;
    asm("{ .reg .u64 t; cvta.to.shared.u64 t, %1; cvt.u32.u64 %0, t; }"
        : "=r"(a) : "l"(p));
    return a;
}
__device__ __forceinline__ uint32_t tf32r(float x) {
    uint32_t u;
    asm("cvt.rna.tf32.f32 %0, %1;" : "=r"(u) : "f"(x));
    return u;
}
__device__ __forceinline__ void cp16(uint32_t dst, const void* src) {
    asm volatile("cp.async.ca.shared.global [%0], [%1], 16;"
                 :: "r"(dst), "l"(src));
}
#define CP_COMMIT() asm volatile("cp.async.commit_group;" ::: "memory")
#define CP_WAIT(n)  asm volatile("cp.async.wait_group %0;" :: "n"(n) : "memory")

__device__ __forceinline__ void mma_tf32(float* c, const uint32_t* a,
                                         const uint32_t* b) {
    asm volatile(
        "mma.sync.aligned.m16n8k8.row.col.f32.tf32.tf32.f32 "
        "{%0,%1,%2,%3}, {%4,%5,%6,%7}, {%8,%9}, {%0,%1,%2,%3};"
        : "+f"(c[0]), "+f"(c[1]), "+f"(c[2]), "+f"(c[3])
        : "r"(a[0]), "r"(a[1]), "r"(a[2]), "r"(a[3]), "r"(b[0]), "r"(b[1]));
}

// ============================================================
// tf32 pre-round pass (elementwise, float4)
// ============================================================
__global__ void round_kernel(const float* __restrict__ in,
                             float* __restrict__ out, int n4) {
    int i = blockIdx.x * blockDim.x + threadIdx.x;
    if (i >= n4) return;
    float4 v = ((const float4*)in)[i];
    v.x = __uint_as_float(tf32r(v.x));
    v.y = __uint_as_float(tf32r(v.y));
    v.z = __uint_as_float(tf32r(v.z));
    v.w = __uint_as_float(tf32r(v.w));
    ((float4*)out)[i] = v;
}

// ============================================================
// Kernel A: competition gating
// ============================================================
__global__ void comp_kernel(const float* __restrict__ x,
                            const float* __restrict__ wc) {
    int gtid = blockIdx.x * blockDim.x + threadIdx.x;
    int t    = gtid >> 5;
    int lane = gtid & 31;
    if (t >= TOK) return;
    const float* xr = x + (size_t)t * 1024;

    float logit[8];
#pragma unroll
    for (int n = 0; n < 8; n++) {
        const float* xb = xr + n * 128;
        const float* wb = wc + n * 128;
        float p = xb[lane]      * wb[lane]
                + xb[lane + 32] * wb[lane + 32]
                + xb[lane + 64] * wb[lane + 64]
                + xb[lane + 96] * wb[lane + 96];
#pragma unroll
        for (int o = 16; o > 0; o >>= 1) p += __shfl_xor_sync(0xffffffffu, p, o);
        logit[n] = p;
    }
    float mx = logit[0];
#pragma unroll
    for (int n = 1; n < 8; n++) mx = fmaxf(mx, logit[n]);
    float s = 0.f, ev = 0.f;
#pragma unroll
    for (int n = 0; n < 8; n++) {
        float e = __expf(logit[n] - mx);
        s += e;
        if (lane == n) ev = e;
    }
    if (lane < 8) g_comp[t * 8 + lane] = ev / s;
}

// ============================================================
// tf32 mma.sync block-GEMM. Operands pre-rounded to tf32 in gmem.
//   template MT = CTA m-tile (128 or 64). 256 threads.
//   3-stage cp.async pipeline, 1 sync per k-chunk of 32.
// ============================================================
#define AS_STRIDE 36
#define BS_STRIDE 136

template<int MT>
__global__ __launch_bounds__(256, 2)
void gemm_mma(const float* __restrict__ Abase, int lda, int a_blk,
              const float* __restrict__ W0, const float* __restrict__ W1,
              const float* __restrict__ W2, int ldb, int w_blk, int TPM,
              float* __restrict__ C0, float* __restrict__ C1,
              float* __restrict__ C2, int ldc, int c_blk,
              int KC, const float* __restrict__ comp) {
    constexpr int A_BUF = MT * AS_STRIDE;
    constexpr int B_BUF = 32 * BS_STRIDE;
    constexpr int STG   = A_BUF + B_BUF;
    constexpr int NWM   = MT / 32;        // warp rows
    constexpr int NWN   = 8 / NWM;        // warp cols
    constexpr int WNW   = 128 / NWN;      // warp col width
    constexpr int JN    = WNW / 8;        // n-fragments per warp

    extern __shared__ __align__(16) float sm[];
    const uint32_t sbase = smem_u32(sm);

    const int tid  = threadIdx.x;
    const int wid  = tid >> 5;
    const int lane = tid & 31;
    const int wm   = wid % NWM;
    const int wn   = wid / NWM;
    const int g    = lane >> 2;
    const int t    = lane & 3;

    const int mt   = blockIdx.x;
    const int yy   = blockIdx.y;
    const int zb   = blockIdx.z;
    const int mat  = yy / TPM;
    const int col0 = (yy % TPM) * 128;

    const float* W = (mat == 0 ? W0 : (mat == 1 ? W1 : W2)) +
                     (size_t)zb * w_blk + col0;
    float* C = (mat == 0 ? C0 : (mat == 1 ? C1 : C2)) +
               (size_t)zb * c_blk + col0;
    const float* A = Abase + (size_t)mt * MT * lda + (size_t)zb * a_blk;

    const int a_m  = tid >> 3;
    const int a_k4 = tid & 7;
    const int b_k  = tid >> 5;
    const int b_e4 = tid & 31;

    float acc[2][JN][4];
#pragma unroll
    for (int i = 0; i < 2; i++)
#pragma unroll
        for (int j = 0; j < JN; j++)
#pragma unroll
            for (int c = 0; c < 4; c++) acc[i][j][c] = 0.f;

    auto issue_chunk = [&](int kc) {
        const int st = kc % 3;
        const uint32_t ad = sbase + (uint32_t)(st * STG) * 4;
        const uint32_t bd = ad + (uint32_t)A_BUF * 4;
        const int k0 = kc * 32;
#pragma unroll
        for (int p = 0; p < MT / 32; p++) {
            int m = a_m + p * 32;
            cp16(ad + (uint32_t)(m * AS_STRIDE + a_k4 * 4) * 4,
                 A + (size_t)m * lda + k0 + a_k4 * 4);
        }
#pragma unroll
        for (int p = 0; p < 4; p++) {
            int k = b_k + p * 8;
            cp16(bd + (uint32_t)(k * BS_STRIDE + b_e4 * 4) * 4,
                 W + (size_t)(k0 + k) * ldb + b_e4 * 4);
        }
    };

    // prologue: 2 chunks in flight
    issue_chunk(0);
    CP_COMMIT();
    if (KC > 1) { issue_chunk(1); CP_COMMIT(); }

    for (int kc = 0; kc < KC; kc++) {
        if (kc + 1 < KC) { CP_WAIT(1); } else { CP_WAIT(0); }
        __syncthreads();
        if (kc + 2 < KC) { issue_chunk(kc + 2); CP_COMMIT(); }

        const float* as = sm + (kc % 3) * STG;
        const float* bs = as + A_BUF;
#pragma unroll
        for (int ks = 0; ks < 4; ks++) {
            const int kk = ks * 8;
            uint32_t af[2][4];
#pragma unroll
            for (int i = 0; i < 2; i++) {
                const int r0 = wm * 32 + i * 16;
                af[i][0] = __float_as_uint(as[(r0 + g)     * AS_STRIDE + kk + t]);
                af[i][1] = __float_as_uint(as[(r0 + g + 8) * AS_STRIDE + kk + t]);
                af[i][2] = __float_as_uint(as[(r0 + g)     * AS_STRIDE + kk + t + 4]);
                af[i][3] = __float_as_uint(as[(r0 + g + 8) * AS_STRIDE + kk + t + 4]);
            }
            uint32_t bf[JN][2];
#pragma unroll
            for (int j = 0; j < JN; j++) {
                const int c = wn * WNW + j * 8 + g;
                bf[j][0] = __float_as_uint(bs[(kk + t)     * BS_STRIDE + c]);
                bf[j][1] = __float_as_uint(bs[(kk + t + 4) * BS_STRIDE + c]);
            }
#pragma unroll
            for (int i = 0; i < 2; i++)
#pragma unroll
                for (int j = 0; j < JN; j++)
                    mma_tf32(acc[i][j], af[i], bf[j]);
        }
    }

    // ---- epilogue ----
#pragma unroll
    for (int i = 0; i < 2; i++) {
        const int r0 = mt * MT + wm * 32 + i * 16 + g;
        const int r1 = r0 + 8;
        float sc0 = 1.f, sc1 = 1.f;
        if (comp) { sc0 = comp[r0 * 8 + zb]; sc1 = comp[r1 * 8 + zb]; }
        float* Cr0 = C + (size_t)r0 * ldc;
        float* Cr1 = C + (size_t)r1 * ldc;
#pragma unroll
        for (int j = 0; j < JN; j++) {
            const int c = wn * WNW + j * 8 + 2 * t;
            float2 v0 = make_float2(acc[i][j][0] * sc0, acc[i][j][1] * sc0);
            float2 v1 = make_float2(acc[i][j][2] * sc1, acc[i][j][3] * sc1);
            *(float2*)(Cr0 + c) = v0;
            *(float2*)(Cr1 + c) = v1;
        }
    }
}

// ============================================================
// Kernel C: block-attention per token; stores g_o tf32-rounded
// ============================================================
#define SMEM_ATTN ((12*8*65 + 12*8*65 + 12*8*64 + 12*64) * 4)

__global__ void attn_kernel(float* __restrict__ out) {
    extern __shared__ float smf[];
    float* sq = smf;
    float* sk = sq + 6240;
    float* sv = sk + 6240;
    float* ss = sv + 6144;

    const int t   = blockIdx.x;
    const int tid = threadIdx.x;
    const size_t base = (size_t)t * 6144;

#pragma unroll
    for (int it = 0; it < 16; it++) {
        int idx = it * 384 + tid;
        int nn  = idx / 768;
        int r   = idx - nn * 768;
        int h   = r >> 6;
        int j   = r & 63;
        sq[h * 520 + nn * 65 + j] = g_q[base + idx] * 0.125f;
        sk[h * 520 + nn * 65 + j] = g_k[base + idx];
        sv[h * 512 + nn * 64 + j] = g_v[base + idx];
    }
    __syncthreads();

    const int w    = tid >> 5;
    const int lane = tid & 31;
    float* q = sq + w * 520;
    float* k = sk + w * 520;
    float* v = sv + w * 512;
    float* s = ss + w * 64;

    const int nr = lane >> 3;
    const int mc = lane & 7;

    float s0 = 0.f, s1 = 0.f;
#pragma unroll
    for (int j = 0; j < 64; j++) {
        float kv = k[mc * 65 + j];
        s0 = fmaf(q[nr * 65 + j], kv, s0);
        s1 = fmaf(q[(nr + 4) * 65 + j], kv, s1);
    }
    float m0 = s0, m1 = s1;
#pragma unroll
    for (int o = 1; o < 8; o <<= 1) {
        m0 = fmaxf(m0, __shfl_xor_sync(0xffffffffu, m0, o));
        m1 = fmaxf(m1, __shfl_xor_sync(0xffffffffu, m1, o));
    }
    float e0 = __expf(s0 - m0), e1 = __expf(s1 - m1);
    float d0 = e0, d1 = e1;
#pragma unroll
    for (int o = 1; o < 8; o <<= 1) {
        d0 += __shfl_xor_sync(0xffffffffu, d0, o);
        d1 += __shfl_xor_sync(0xffffffffu, d1, o);
    }
    float a0 = e0 / d0, a1 = e1 / d1;
    s[nr * 8 + mc]       = a0;
    s[(nr + 4) * 8 + mc] = a1;
    __syncwarp();

#pragma unroll
    for (int nn = 0; nn < 8; nn++) {
        float acc0 = 0.f, acc1 = 0.f;
#pragma unroll
        for (int mm = 0; mm < 8; mm++) {
            float av = s[nn * 8 + mm];
            acc0 = fmaf(av, v[mm * 64 + lane], acc0);
            acc1 = fmaf(av, v[mm * 64 + 32 + lane], acc1);
        }
        // store tf32-rounded: feeds the final tf32 GEMM directly
        g_o[base + nn * 768 + w * 64 + lane] =
            __uint_as_float(tf32r(acc0));
        g_o[base + nn * 768 + w * 64 + 32 + lane] =
            __uint_as_float(tf32r(acc1));
    }
    __syncthreads();

    if (tid < 64) {
        float sum = 0.f;
#pragma unroll
        for (int h = 0; h < 12; h++) sum += ss[h * 64 + tid];
        out[4194304 + (size_t)t * 64 + tid] = sum * (1.0f / 12.0f);
    }
}

// ============================================================
// launch
// ============================================================
#define SMEM_G128 (3 * (128 * AS_STRIDE + 32 * BS_STRIDE) * 4)  // 107520
#define SMEM_G64  (3 * (64  * AS_STRIDE + 32 * BS_STRIDE) * 4)  // 79872

extern "C" void kernel_launch(void* const* d_in, const int* in_sizes, int n_in,
                              void* d_out, int out_size) {
    const float* x  = (const float*)d_in[0];
    const float* wc = (const float*)d_in[1];
    const float* wq = (const float*)d_in[2];
    const float* wk = (const float*)d_in[3];
    const float* wv = (const float*)d_in[4];
    const float* wf = (const float*)d_in[5];
    float* out = (float*)d_out;

    float *gq, *gk, *gv, *go, *gc, *gxr, *gwq, *gwk, *gwv, *gwf;
    cudaGetSymbolAddress((void**)&gq, g_q);
    cudaGetSymbolAddress((void**)&gk, g_k);
    cudaGetSymbolAddress((void**)&gv, g_v);
    cudaGetSymbolAddress((void**)&go, g_o);
    cudaGetSymbolAddress((void**)&gc, g_comp);
    cudaGetSymbolAddress((void**)&gxr, g_xr);
    cudaGetSymbolAddress((void**)&gwq, g_wqr);
    cudaGetSymbolAddress((void**)&gwk, g_wkr);
    cudaGetSymbolAddress((void**)&gwv, g_wvr);
    cudaGetSymbolAddress((void**)&gwf, g_wfr);

    cudaFuncSetAttribute(attn_kernel,
                         cudaFuncAttributeMaxDynamicSharedMemorySize, SMEM_ATTN);
    cudaFuncSetAttribute(gemm_mma<128>,
                         cudaFuncAttributeMaxDynamicSharedMemorySize, SMEM_G128);
    cudaFuncSetAttribute(gemm_mma<64>,
                         cudaFuncAttributeMaxDynamicSharedMemorySize, SMEM_G64);

    // pre-round operands to tf32 (zero-mean rna rounding)
    round_kernel<<<4096, 256>>>(x,  gxr, 1048576);
    round_kernel<<<768, 256>>>(wq, gwq, 196608);
    round_kernel<<<768, 256>>>(wk, gwk, 196608);
    round_kernel<<<768, 256>>>(wv, gwv, 196608);
    round_kernel<<<768, 256>>>(wf, gwf, 196608);

    // A: gating (uses full-precision x)
    comp_kernel<<<512, 256>>>(x, wc);

    // B: fused QKV tf32 GEMMs. 18 = 3 matrices x 6 col-tiles. K=128 -> KC=4.
    dim3 gB(32, 18, 8);
    gemm_mma<128><<<gB, 256, SMEM_G128>>>(
        gxr, 1024, 128,
        gwq, gwk, gwv, 768, 98304, 6,
        gq, gk, gv, 6144, 768,
        4, gc);

    // C: attention over the block axis + score_mean
    attn_kernel<<<TOK, 384, SMEM_ATTN>>>(out);

    // D: final tf32 GEMM. K=768 -> KC=24, m-tile 64 for occupancy.
    dim3 gD(64, 1, 8);
    gemm_mma<64><<<gD, 256, SMEM_G64>>>(
        go, 6144, 768,
        gwf, gwf, gwf, 128, 98304, 1,
        out, out, out, 1024, 128,
        24, nullptr);
}